// round 12
// baseline (speedup 1.0000x reference)
#include <cuda_runtime.h>
#include <cuda_fp16.h>
#include <cstdint>

#define HH 48
#define WW 96
#define HW 4608
#define HEADS 4
#define DH 128
#define C_IN 256
#define C_ATT 64
#define C_MID 256
#define C_OUT 19
#define EPS 1e-5f

#define TQ 64
#define TK 64
#define QK_STRW 68   // K smem word stride (136 halves, 272B)
#define VT_STRW 36   // V^T smem word stride (72 halves, 144B)
#define BW_STR 98
#define BH_STR 50
#define NREL 288     // packed rel rows: [0,191)=rel_w, 191 pad, [192,287)=rel_h, 287 pad

// conv GEMM smem strides
#define WT_STR 36
#define XT_STR 136

// ---- scratch (no allocations allowed) ----
__device__ float  g_h1[C_ATT * HW];
__device__ __half g_qh[HEADS * HW * DH];    // fp16 [h][i][d], scaled by rsqrt(DH)*log2e
__device__ __half g_kh[HEADS * HW * DH];    // fp16 [h][i][d]
__device__ __half g_vT[HEADS * DH * HW];    // fp16 [h][d][i]  (transposed)
__device__ __half g_relh[NREL * DH];        // packed fp16 rel tables
__device__ float  g_Rw[HEADS * HW * 192];   // q . rel_w[j]
__device__ float  g_Rh[HEADS * HW * 96];    // q . rel_h[j]
__device__ float  g_ao[HEADS * DH * HW];    // [h*128+d][i]
__device__ float  g_fm[C_MID * HW];

__device__ __forceinline__ uint32_t f2tf(float f) {
    uint32_t u;
    asm("cvt.rna.tf32.f32 %0, %1;" : "=r"(u) : "f"(f));
    return u;
}
__device__ __forceinline__ float4 f2tf4(float4 a) {
    a.x = __uint_as_float(f2tf(a.x)); a.y = __uint_as_float(f2tf(a.y));
    a.z = __uint_as_float(f2tf(a.z)); a.w = __uint_as_float(f2tf(a.w));
    return a;
}
__device__ __forceinline__ uint32_t packh2(float lo, float hi) {
    __half2 h = __floats2half2_rn(lo, hi);
    return *(uint32_t*)&h;
}
__device__ __forceinline__ float ex2f(float x) {
    float r;
    asm("ex2.approx.f32 %0, %1;" : "=f"(r) : "f"(x));
    return r;
}

__device__ __forceinline__ void mma8(float4& d, uint32_t a0, uint32_t a1,
                                     uint32_t a2, uint32_t a3,
                                     uint32_t b0, uint32_t b1) {
    asm volatile(
        "mma.sync.aligned.m16n8k8.row.col.f32.tf32.tf32.f32 "
        "{%0,%1,%2,%3},{%4,%5,%6,%7},{%8,%9},{%0,%1,%2,%3};"
        : "+f"(d.x), "+f"(d.y), "+f"(d.z), "+f"(d.w)
        : "r"(a0), "r"(a1), "r"(a2), "r"(a3), "r"(b0), "r"(b1));
}
__device__ __forceinline__ void mma16(float4& d, uint32_t a0, uint32_t a1,
                                      uint32_t a2, uint32_t a3,
                                      uint32_t b0, uint32_t b1) {
    asm volatile(
        "mma.sync.aligned.m16n8k16.row.col.f32.f16.f16.f32 "
        "{%0,%1,%2,%3},{%4,%5,%6,%7},{%8,%9},{%0,%1,%2,%3};"
        : "+f"(d.x), "+f"(d.y), "+f"(d.z), "+f"(d.w)
        : "r"(a0), "r"(a1), "r"(a2), "r"(a3), "r"(b0), "r"(b1));
}

#define CP_A16(dst_u32, src_ptr) \
    asm volatile("cp.async.ca.shared.global [%0], [%1], 16;" \
                 :: "r"(dst_u32), "l"(src_ptr))
#define CP_COMMIT() asm volatile("cp.async.commit_group;")
#define CP_WAIT0()  asm volatile("cp.async.wait_group 0;" ::: "memory")
#define CP_WAIT1()  asm volatile("cp.async.wait_group 1;" ::: "memory")

// =====================================================================
// Generic conv GEMM (unchanged, proven)
// =====================================================================
template<int KDIM, int OREAL, int EPI, int XSRC, int YDST>
__global__ __launch_bounds__(256)
void k_conv(const float* __restrict__ W, const float* __restrict__ Xp,
            float* __restrict__ Yp,
            const float* __restrict__ e0, const float* __restrict__ e1,
            const float* __restrict__ e2, const float* __restrict__ e3,
            const float* __restrict__ e4) {
    const float* X = (XSRC == 0) ? Xp : (XSRC == 2) ? g_ao : g_fm;
    float* Y = (YDST == 0) ? Yp : (YDST == 1) ? g_h1 : g_fm;

    __shared__ float sw[64 * WT_STR];
    __shared__ float sx[32 * XT_STR];

    int tid = threadIdx.x, wid = tid >> 5, lane = tid & 31;
    int gid = lane >> 2, tig = lane & 3;
    int p0 = blockIdx.x * 128, bo0 = blockIdx.y * 64;
    int mo0 = (wid >> 1) * 16, np0 = (wid & 1) * 64;

    constexpr int NC = KDIM / 32;

    int wrow[2], wcol[2], xrow[4], xcol[4];
#pragma unroll
    for (int q = 0; q < 2; q++) { int f = q * 256 + tid; wrow[q] = f >> 3; wcol[q] = (f & 7) * 4; }
#pragma unroll
    for (int q = 0; q < 4; q++) { int f = q * 256 + tid; xrow[q] = f >> 5; xcol[q] = (f & 31) * 4; }

    float4 rw[2], rx[4];
#pragma unroll
    for (int q = 0; q < 2; q++) {
        if (OREAL % 64 == 0 || bo0 + wrow[q] < OREAL)
            rw[q] = *(const float4*)&W[(bo0 + wrow[q]) * KDIM + wcol[q]];
        else rw[q] = make_float4(0.f, 0.f, 0.f, 0.f);
    }
#pragma unroll
    for (int q = 0; q < 4; q++)
        rx[q] = *(const float4*)&X[xrow[q] * HW + p0 + xcol[q]];

    float4 acc[8];
#pragma unroll
    for (int nt = 0; nt < 8; nt++) acc[nt] = make_float4(0.f, 0.f, 0.f, 0.f);

    const uint32_t* swu = (const uint32_t*)sw;
    const uint32_t* sxu = (const uint32_t*)sx;

    for (int ch = 0; ch < NC; ch++) {
        __syncthreads();
#pragma unroll
        for (int q = 0; q < 2; q++)
            *(float4*)&sw[wrow[q] * WT_STR + wcol[q]] = f2tf4(rw[q]);
#pragma unroll
        for (int q = 0; q < 4; q++)
            *(float4*)&sx[xrow[q] * XT_STR + xcol[q]] = f2tf4(rx[q]);
        __syncthreads();

        if (ch + 1 < NC) {
            int c0 = (ch + 1) * 32;
#pragma unroll
            for (int q = 0; q < 2; q++) {
                if (OREAL % 64 == 0 || bo0 + wrow[q] < OREAL)
                    rw[q] = *(const float4*)&W[(bo0 + wrow[q]) * KDIM + c0 + wcol[q]];
                else rw[q] = make_float4(0.f, 0.f, 0.f, 0.f);
            }
#pragma unroll
            for (int q = 0; q < 4; q++)
                rx[q] = *(const float4*)&X[(c0 + xrow[q]) * HW + p0 + xcol[q]];
        }

#pragma unroll
        for (int kk = 0; kk < 4; kk++) {
            int ca = kk * 8;
            uint32_t a0 = swu[(mo0 + gid) * WT_STR + ca + tig];
            uint32_t a1 = swu[(mo0 + gid + 8) * WT_STR + ca + tig];
            uint32_t a2 = swu[(mo0 + gid) * WT_STR + ca + tig + 4];
            uint32_t a3 = swu[(mo0 + gid + 8) * WT_STR + ca + tig + 4];
#pragma unroll
            for (int nt = 0; nt < 8; nt++) {
                uint32_t b0 = sxu[(ca + tig) * XT_STR + np0 + nt * 8 + gid];
                uint32_t b1 = sxu[(ca + tig + 4) * XT_STR + np0 + nt * 8 + gid];
                mma8(acc[nt], a0, a1, a2, a3, b0, b1);
            }
        }
    }

    int ra = bo0 + mo0 + gid, rb = ra + 8;
    float sca = 0.f, ofa = 0.f, scb = 0.f, ofb = 0.f;
    if (EPI == 0 || EPI == 1) {
        sca = e0[ra] * rsqrtf(e3[ra] + EPS); ofa = e1[ra] - e2[ra] * sca;
        scb = e0[rb] * rsqrtf(e3[rb] + EPS); ofb = e1[rb] - e2[rb] * scb;
    } else {
        sca = 1.f; scb = 1.f;
        ofa = (OREAL % 64 == 0 || ra < OREAL) ? e0[ra] : 0.f;
        ofb = (OREAL % 64 == 0 || rb < OREAL) ? e0[rb] : 0.f;
    }
#pragma unroll
    for (int nt = 0; nt < 8; nt++) {
        int p = p0 + np0 + nt * 8 + 2 * tig;
        float2 va, vb;
        va.x = acc[nt].x * sca + ofa; va.y = acc[nt].y * sca + ofa;
        vb.x = acc[nt].z * scb + ofb; vb.y = acc[nt].w * scb + ofb;
        if (EPI == 1) {
            float2 xa = *(const float2*)&e4[ra * HW + p];
            float2 xb = *(const float2*)&e4[rb * HW + p];
            va.x += xa.x; va.y += xa.y; vb.x += xb.x; vb.y += xb.y;
        }
        if (EPI != 2) {
            va.x = fmaxf(va.x, 0.f); va.y = fmaxf(va.y, 0.f);
            vb.x = fmaxf(vb.x, 0.f); vb.y = fmaxf(vb.y, 0.f);
        }
        if (OREAL % 64 == 0 || ra < OREAL) *(float2*)&Y[ra * HW + p] = va;
        if (OREAL % 64 == 0 || rb < OREAL) *(float2*)&Y[rb * HW + p] = vb;
    }
}

// =====================================================================
// Pack rel_w/rel_h into one fp16 table (288 rows x 128)
// =====================================================================
__global__ void k_relcvt(const float* __restrict__ rel_h,
                         const float* __restrict__ rel_w) {
    int idx = blockIdx.x * 256 + threadIdx.x;
    if (idx >= NREL * DH) return;
    int j = idx >> 7, d = idx & 127;
    float v = 0.f;
    if (j < 191)       v = rel_w[j * DH + d];
    else if (j >= 192 && j < 287) v = rel_h[(j - 192) * DH + d];
    g_relh[idx] = __float2half(v);
}

// =====================================================================
// k_qkv: q scaled by rsqrt(DH)*log2(e); writes q/k fp16, v fp16 transposed
// =====================================================================
__global__ __launch_bounds__(256)
void k_qkvmma(const float* __restrict__ W) {
    __shared__ float sw[64 * WT_STR];
    __shared__ float sx[32 * XT_STR];

    int tid = threadIdx.x, wid = tid >> 5, lane = tid & 31;
    int gid = lane >> 2, tig = lane & 3;
    int p0 = blockIdx.x * 128, bo0 = blockIdx.y * 64;
    int mp0 = wid * 16;

    int wrow[2], wcol[2], xrow[4], xcol[4];
#pragma unroll
    for (int q = 0; q < 2; q++) { int f = q * 256 + tid; wrow[q] = f >> 3; wcol[q] = (f & 7) * 4; }
#pragma unroll
    for (int q = 0; q < 4; q++) { int f = q * 256 + tid; xrow[q] = f >> 5; xcol[q] = (f & 31) * 4; }

    float4 rw[2], rx[4];
#pragma unroll
    for (int q = 0; q < 2; q++)
        rw[q] = *(const float4*)&W[(bo0 + wrow[q]) * C_ATT + wcol[q]];
#pragma unroll
    for (int q = 0; q < 4; q++)
        rx[q] = *(const float4*)&g_h1[xrow[q] * HW + p0 + xcol[q]];

    float4 acc[8];
#pragma unroll
    for (int nt = 0; nt < 8; nt++) acc[nt] = make_float4(0.f, 0.f, 0.f, 0.f);

    const uint32_t* swu = (const uint32_t*)sw;
    const uint32_t* sxu = (const uint32_t*)sx;

    for (int ch = 0; ch < 2; ch++) {
        __syncthreads();
#pragma unroll
        for (int q = 0; q < 2; q++)
            *(float4*)&sw[wrow[q] * WT_STR + wcol[q]] = f2tf4(rw[q]);
#pragma unroll
        for (int q = 0; q < 4; q++)
            *(float4*)&sx[xrow[q] * XT_STR + xcol[q]] = f2tf4(rx[q]);
        __syncthreads();
        if (ch == 0) {
#pragma unroll
            for (int q = 0; q < 2; q++)
                rw[q] = *(const float4*)&W[(bo0 + wrow[q]) * C_ATT + 32 + wcol[q]];
#pragma unroll
            for (int q = 0; q < 4; q++)
                rx[q] = *(const float4*)&g_h1[(32 + xrow[q]) * HW + p0 + xcol[q]];
        }
#pragma unroll
        for (int kk = 0; kk < 4; kk++) {
            int ca = kk * 8;
            uint32_t a0 = sxu[(ca + tig) * XT_STR + mp0 + gid];
            uint32_t a1 = sxu[(ca + tig) * XT_STR + mp0 + gid + 8];
            uint32_t a2 = sxu[(ca + tig + 4) * XT_STR + mp0 + gid];
            uint32_t a3 = sxu[(ca + tig + 4) * XT_STR + mp0 + gid + 8];
#pragma unroll
            for (int nt = 0; nt < 8; nt++) {
                uint32_t b0 = swu[(nt * 8 + gid) * WT_STR + ca + tig];
                uint32_t b1 = swu[(nt * 8 + gid) * WT_STR + ca + tig + 4];
                mma8(acc[nt], a0, a1, a2, a3, b0, b1);
            }
        }
    }

    int part = bo0 >> 9;
    int head = (bo0 & 511) >> 7;
    int dh0  = bo0 & 127;
    int pa = p0 + mp0 + gid, pb = pa + 8;
#pragma unroll
    for (int nt = 0; nt < 8; nt++) {
        int dh = dh0 + nt * 8 + 2 * tig;
        float ax = acc[nt].x, ay = acc[nt].y, bx = acc[nt].z, by = acc[nt].w;
        if (part == 0) {
            const float sc = 0.08838834764831845f * 1.4426950408889634f;
            ax *= sc; ay *= sc; bx *= sc; by *= sc;
            *(uint32_t*)&g_qh[(head * HW + pa) * DH + dh] = packh2(ax, ay);
            *(uint32_t*)&g_qh[(head * HW + pb) * DH + dh] = packh2(bx, by);
        } else if (part == 1) {
            *(uint32_t*)&g_kh[(head * HW + pa) * DH + dh] = packh2(ax, ay);
            *(uint32_t*)&g_kh[(head * HW + pb) * DH + dh] = packh2(bx, by);
        } else {
            g_vT[(head * DH + dh)     * HW + pa] = __float2half(ax);
            g_vT[(head * DH + dh + 1) * HW + pa] = __float2half(ay);
            g_vT[(head * DH + dh)     * HW + pb] = __float2half(bx);
            g_vT[(head * DH + dh + 1) * HW + pb] = __float2half(by);
        }
    }
}

// =====================================================================
// k_rel: R[i][j] = q_i . rel[j]  (fp16 mma, fp32 out)
// =====================================================================
__global__ __launch_bounds__(128)
void k_rel() {
    extern __shared__ char smc[];
    __half* qsh = (__half*)smc;                  // 64 x 136 halves
    __half* rsh = (__half*)(smc + 17408);        // 144 x 136 halves

    int tid = threadIdx.x, wid = tid >> 5, lane = tid & 31;
    int gid = lane >> 2, tig = lane & 3;
    int h = blockIdx.y, r0 = blockIdx.x * 64, c0 = blockIdx.z * 144;
    int wr0 = wid * 16;

    uint32_t q_sm = (uint32_t)__cvta_generic_to_shared(qsh);
    uint32_t r_sm = (uint32_t)__cvta_generic_to_shared(rsh);

    const __half* gq = g_qh + (h * HW + r0) * DH;
    for (int e = tid; e < 64 * 16; e += 128) {
        int r = e >> 4, c = e & 15;
        CP_A16(q_sm + r * 272 + c * 16, gq + r * DH + c * 8);
    }
    const __half* gr = g_relh + c0 * DH;
    for (int e = tid; e < 144 * 16; e += 128) {
        int r = e >> 4, c = e & 15;
        CP_A16(r_sm + r * 272 + c * 16, gr + r * DH + c * 8);
    }
    CP_COMMIT(); CP_WAIT0();
    __syncthreads();

    uint32_t qf[8][4];
    const uint32_t* qw = (const uint32_t*)qsh;
#pragma unroll
    for (int kk = 0; kk < 8; kk++) {
        int cw = kk * 8 + tig;
        qf[kk][0] = qw[(wr0 + gid) * QK_STRW + cw];
        qf[kk][1] = qw[(wr0 + gid + 8) * QK_STRW + cw];
        qf[kk][2] = qw[(wr0 + gid) * QK_STRW + cw + 4];
        qf[kk][3] = qw[(wr0 + gid + 8) * QK_STRW + cw + 4];
    }

    float4 s[18];
#pragma unroll
    for (int nt = 0; nt < 18; nt++) s[nt] = make_float4(0.f, 0.f, 0.f, 0.f);
    const uint32_t* rw = (const uint32_t*)rsh;
#pragma unroll
    for (int kk = 0; kk < 8; kk++) {
        int cw = kk * 8 + tig;
#pragma unroll
        for (int nt = 0; nt < 18; nt++) {
            uint32_t b0 = rw[(nt * 8 + gid) * QK_STRW + cw];
            uint32_t b1 = rw[(nt * 8 + gid) * QK_STRW + cw + 4];
            mma16(s[nt], qf[kk][0], qf[kk][1], qf[kk][2], qf[kk][3], b0, b1);
        }
    }

    int ia = h * HW + r0 + wr0 + gid;
    int ib = ia + 8;
#pragma unroll
    for (int nt = 0; nt < 18; nt++) {
        int j = c0 + nt * 8 + 2 * tig;
        if (j < 192) {
            *(float2*)&g_Rw[ia * 192 + j] = make_float2(s[nt].x, s[nt].y);
            *(float2*)&g_Rw[ib * 192 + j] = make_float2(s[nt].z, s[nt].w);
        } else {
            int j2 = j - 192;
            *(float2*)&g_Rh[ia * 96 + j2] = make_float2(s[nt].x, s[nt].y);
            *(float2*)&g_Rh[ib * 96 + j2] = make_float2(s[nt].z, s[nt].w);
        }
    }
}

// =====================================================================
// Kernel C: flash attention, fp16 mma, double-buffered, precomputed bias,
// NO max subtraction (scores are O(1) by construction).
// =====================================================================
__global__ __launch_bounds__(128, 2)
void k_attn() {
    extern __shared__ char smc[];
    // [0,17408) K buf0 ; [17408,35840) V buf0 ; [35840,54272) V buf1
    // [54272,71680) Q staging == K buf1 ; [71680,96768) Bw ; [96768,109568) Bh
    __half* qsh = (__half*)(smc + 54272);
    float*  Bw  = (float*)(smc + 71680);
    float*  Bh  = (float*)(smc + 96768);

    uint32_t base = (uint32_t)__cvta_generic_to_shared(smc);
    uint32_t k_sm[2] = { base,         base + 54272 };
    uint32_t v_sm[2] = { base + 17408, base + 35840 };
    const uint32_t* kw_[2] = { (const uint32_t*)smc, (const uint32_t*)(smc + 54272) };
    const uint32_t* vw_[2] = { (const uint32_t*)(smc + 17408), (const uint32_t*)(smc + 35840) };

    int tid  = threadIdx.x;
    int h    = blockIdx.y;
    int r0   = blockIdx.x * TQ;
    int wid  = tid >> 5, lane = tid & 31;
    int gid  = lane >> 2, tig = lane & 3;
    int wr0  = wid * 16;

    const __half* gkh = g_kh + h * HW * DH;
    const __half* gvh = g_vT + h * DH * HW;

    // --- preload Q + tile-0 K/V ---
    {
        const __half* gq = g_qh + (h * HW + r0) * DH;
        uint32_t q_sm = base + 54272;
        for (int e = tid; e < TQ * 16; e += 128) {
            int r = e >> 4, c = e & 15;
            CP_A16(q_sm + r * 272 + c * 16, gq + r * DH + c * 8);
        }
        for (int e = tid; e < TK * 16; e += 128) {
            int r = e >> 4, c = e & 15;
            CP_A16(k_sm[0] + r * 272 + c * 16, gkh + r * DH + c * 8);
        }
        for (int e = tid; e < DH * 8; e += 128) {
            int r = e >> 3, c = e & 7;
            CP_A16(v_sm[0] + r * 144 + c * 16, gvh + r * HW + c * 8);
        }
    }
    CP_COMMIT();

    // --- bias tables: contiguous slice copies from precomputed R ---
    for (int e = tid; e < TQ * WW; e += 128) {
        int r = e / WW, wk = e % WW;
        int i = r0 + r, wq = i % WW;
        Bw[r * BW_STR + wk] = g_Rw[(h * HW + i) * 192 + (WW - 1 - wq) + wk];
    }
    for (int e = tid; e < TQ * HH; e += 128) {
        int r = e / HH, hk = e % HH;
        int i = r0 + r, hq = i / WW;
        Bh[r * BH_STR + hk] = g_Rh[(h * HW + i) * 96 + (HH - 1 - hq) + hk];
    }
    CP_WAIT0();
    __syncthreads();

    // --- Q a-fragments from qsh ---
    uint32_t qf[8][4];
    const uint32_t* qw = (const uint32_t*)qsh;
#pragma unroll
    for (int kk = 0; kk < 8; kk++) {
        int cw = kk * 8 + tig;
        qf[kk][0] = qw[(wr0 + gid) * QK_STRW + cw];
        qf[kk][1] = qw[(wr0 + gid + 8) * QK_STRW + cw];
        qf[kk][2] = qw[(wr0 + gid) * QK_STRW + cw + 4];
        qf[kk][3] = qw[(wr0 + gid + 8) * QK_STRW + cw + 4];
    }
    __syncthreads();   // qsh consumed; region is now K buf1

    constexpr int NT = HW / TK;   // 72

    // --- prefetch tile 1 into buf1 ---
    {
        const __half* gk = gkh + TK * DH;
        for (int e = tid; e < TK * 16; e += 128) {
            int r = e >> 4, c = e & 15;
            CP_A16(k_sm[1] + r * 272 + c * 16, gk + r * DH + c * 8);
        }
        const __half* gv = gvh + TK;
        for (int e = tid; e < DH * 8; e += 128) {
            int r = e >> 3, c = e & 7;
            CP_A16(v_sm[1] + r * 144 + c * 16, gv + r * HW + c * 8);
        }
    }
    CP_COMMIT();

    float4 o[16];
#pragma unroll
    for (int nt = 0; nt < 16; nt++) o[nt] = make_float4(0.f, 0.f, 0.f, 0.f);
    float l_a = 0.f, l_b = 0.f;

    int ra = wr0 + gid, rb = ra + 8;

    for (int kt = 0; kt < NT; kt++) {
        int cur = kt & 1;
        if (kt > 0) {
            if (kt + 1 < NT) {
                int nxt = (kt + 1) & 1;
                const __half* gk = gkh + (kt + 1) * TK * DH;
                for (int e = tid; e < TK * 16; e += 128) {
                    int r = e >> 4, c = e & 15;
                    CP_A16(k_sm[nxt] + r * 272 + c * 16, gk + r * DH + c * 8);
                }
                const __half* gv = gvh + (kt + 1) * TK;
                for (int e = tid; e < DH * 8; e += 128) {
                    int r = e >> 3, c = e & 7;
                    CP_A16(v_sm[nxt] + r * 144 + c * 16, gv + r * HW + c * 8);
                }
                CP_COMMIT();
                CP_WAIT1();
            } else {
                CP_WAIT0();
            }
            __syncthreads();
        }

        // --- S = Q @ K^T ---
        float4 s[8];
#pragma unroll
        for (int nt = 0; nt < 8; nt++) s[nt] = make_float4(0.f, 0.f, 0.f, 0.f);
        const uint32_t* kw = kw_[cur];
#pragma unroll
        for (int kk = 0; kk < 8; kk++) {
            int cw = kk * 8 + tig;
#pragma unroll
            for (int nt = 0; nt < 8; nt++) {
                uint32_t b0 = kw[(nt * 8 + gid) * QK_STRW + cw];
                uint32_t b1 = kw[(nt * 8 + gid) * QK_STRW + cw + 4];
                mma16(s[nt], qf[kk][0], qf[kk][1], qf[kk][2], qf[kk][3], b0, b1);
            }
        }

        // --- bias add + exp2 (no max subtraction; |s| = O(1)) ---
        int j0 = kt * TK;
        int h0 = j0 / WW, w0 = j0 - WW * h0;
        float bha0 = Bh[ra * BH_STR + h0], bha1 = Bh[ra * BH_STR + h0 + 1];
        float bhb0 = Bh[rb * BH_STR + h0], bhb1 = Bh[rb * BH_STR + h0 + 1];
#pragma unroll
        for (int nt = 0; nt < 8; nt++) {
            int jl = nt * 8 + 2 * tig;
            int w1 = w0 + jl;
            bool wrap = (w1 >= WW);
            int wk0 = wrap ? w1 - WW : w1;
            float bha = wrap ? bha1 : bha0;
            float bhb = wrap ? bhb1 : bhb0;
            float2 ba = *(const float2*)&Bw[ra * BW_STR + wk0];
            float2 bb = *(const float2*)&Bw[rb * BW_STR + wk0];
            s[nt].x = ex2f(s[nt].x + ba.x + bha);
            s[nt].y = ex2f(s[nt].y + ba.y + bha);
            s[nt].z = ex2f(s[nt].z + bb.x + bhb);
            s[nt].w = ex2f(s[nt].w + bb.y + bhb);
            l_a += s[nt].x + s[nt].y;
            l_b += s[nt].z + s[nt].w;
        }

        // --- O += P @ V : P register-direct ---
        const uint32_t* vw = vw_[cur];
#pragma unroll
        for (int kk = 0; kk < 4; kk++) {
            uint32_t a0 = packh2(s[2 * kk].x,     s[2 * kk].y);
            uint32_t a1 = packh2(s[2 * kk].z,     s[2 * kk].w);
            uint32_t a2 = packh2(s[2 * kk + 1].x, s[2 * kk + 1].y);
            uint32_t a3 = packh2(s[2 * kk + 1].z, s[2 * kk + 1].w);
            int cw = kk * 8 + tig;
#pragma unroll
            for (int nt = 0; nt < 16; nt++) {
                uint32_t b0 = vw[(nt * 8 + gid) * VT_STRW + cw];
                uint32_t b1 = vw[(nt * 8 + gid) * VT_STRW + cw + 4];
                mma16(o[nt], a0, a1, a2, a3, b0, b1);
            }
        }
        __syncthreads();   // buffer `cur` free for prefetch
    }

    // --- epilogue: single l reduction, normalize ---
    l_a += __shfl_xor_sync(0xffffffffu, l_a, 1);
    l_a += __shfl_xor_sync(0xffffffffu, l_a, 2);
    l_b += __shfl_xor_sync(0xffffffffu, l_b, 1);
    l_b += __shfl_xor_sync(0xffffffffu, l_b, 2);
    float inva = 1.f / l_a, invb = 1.f / l_b;
    int ia = r0 + ra, ib = r0 + rb;
#pragma unroll
    for (int nt = 0; nt < 16; nt++) {
        int d = nt * 8 + 2 * tig;
        g_ao[(h * DH + d)     * HW + ia] = o[nt].x * inva;
        g_ao[(h * DH + d + 1) * HW + ia] = o[nt].y * inva;
        g_ao[(h * DH + d)     * HW + ib] = o[nt].z * invb;
        g_ao[(h * DH + d + 1) * HW + ib] = o[nt].w * invb;
    }
}

// ---------------- launch ----------------
extern "C" void kernel_launch(void* const* d_in, const int* in_sizes, int n_in,
                              void* d_out, int out_size) {
    const float* x      = (const float*)d_in[0];
    const float* w_in   = (const float*)d_in[1];
    const float* bn1_g  = (const float*)d_in[2];
    const float* bn1_b  = (const float*)d_in[3];
    const float* bn1_m  = (const float*)d_in[4];
    const float* bn1_v  = (const float*)d_in[5];
    const float* w_qkv  = (const float*)d_in[6];
    const float* rel_h  = (const float*)d_in[7];
    const float* rel_w  = (const float*)d_in[8];
    const float* w_out  = (const float*)d_in[9];
    const float* bn2_g  = (const float*)d_in[10];
    const float* bn2_b  = (const float*)d_in[11];
    const float* bn2_m  = (const float*)d_in[12];
    const float* bn2_v  = (const float*)d_in[13];
    const float* w_head = (const float*)d_in[14];
    const float* b_head = (const float*)d_in[15];
    float* out = (float*)d_out;

    const int ATTN_SMEM = 109568;
    const int REL_SMEM  = 17408 + 144 * 272;   // 56576

    cudaFuncSetAttribute(k_attn, cudaFuncAttributeMaxDynamicSharedMemorySize, ATTN_SMEM);
    cudaFuncSetAttribute(k_rel,  cudaFuncAttributeMaxDynamicSharedMemorySize, REL_SMEM);

    k_relcvt<<<(NREL * DH + 255) / 256, 256>>>(rel_h, rel_w);
    k_conv<256, 64, 0, 0, 1><<<dim3(HW / 128, 1), 256>>>(
        w_in, x, nullptr, bn1_g, bn1_b, bn1_m, bn1_v, nullptr);
    k_qkvmma<<<dim3(HW / 128, (3 * HEADS * DH) / 64), 256>>>(w_qkv);
    k_rel<<<dim3(HW / 64, HEADS, 2), 128, REL_SMEM>>>();
    k_attn<<<dim3(HW / TQ, HEADS), 128, ATTN_SMEM>>>();
    k_conv<512, 256, 1, 2, 3><<<dim3(HW / 128, C_MID / 64), 256>>>(
        w_out, nullptr, nullptr, bn2_g, bn2_b, bn2_m, bn2_v, x);
    k_conv<256, 19, 2, 3, 0><<<dim3(HW / 128, 1), 256>>>(
        w_head, nullptr, out, b_head, nullptr, nullptr, nullptr, nullptr);
}

// round 13
// speedup vs baseline: 1.1954x; 1.1954x over previous
#include <cuda_runtime.h>
#include <cuda_fp16.h>
#include <cstdint>

#define HH 48
#define WW 96
#define HW 4608
#define HEADS 4
#define DH 128
#define C_IN 256
#define C_ATT 64
#define C_MID 256
#define C_OUT 19
#define EPS 1e-5f

#define TQ 64
#define TK 64
#define QK_STRB 272  // K smem row stride bytes (136 halves)
#define QK_STRW 68
#define VT_STRB 144  // V^T smem row stride bytes (72 halves)
#define VT_STRW 36
#define BW_STR 98
#define BH_STR 50
#define NREL 288

// conv GEMM smem strides
#define WT_STR 36
#define XT_STR 136

// ---- scratch (no allocations allowed) ----
__device__ float  g_h1[C_ATT * HW];
__device__ __half g_qh[HEADS * HW * DH];    // fp16 [h][i][d], scaled by rsqrt(DH)*log2e
__device__ __half g_kh[HEADS * HW * DH];    // fp16 [h][i][d]
__device__ __half g_vT[HEADS * DH * HW];    // fp16 [h][d][i]  (transposed)
__device__ __half g_relh[NREL * DH];        // packed fp16 rel tables
__device__ float  g_Rw[HEADS * HW * 192];   // q . rel_w[j]
__device__ float  g_Rh[HEADS * HW * 96];    // q . rel_h[j]
__device__ float  g_ao[HEADS * DH * HW];    // [h*128+d][i]
__device__ float  g_fm[C_MID * HW];

__device__ __forceinline__ uint32_t f2tf(float f) {
    uint32_t u;
    asm("cvt.rna.tf32.f32 %0, %1;" : "=r"(u) : "f"(f));
    return u;
}
__device__ __forceinline__ float4 f2tf4(float4 a) {
    a.x = __uint_as_float(f2tf(a.x)); a.y = __uint_as_float(f2tf(a.y));
    a.z = __uint_as_float(f2tf(a.z)); a.w = __uint_as_float(f2tf(a.w));
    return a;
}
__device__ __forceinline__ uint32_t packh2(float lo, float hi) {
    __half2 h = __floats2half2_rn(lo, hi);
    return *(uint32_t*)&h;
}
__device__ __forceinline__ float ex2f(float x) {
    float r;
    asm("ex2.approx.f32 %0, %1;" : "=f"(r) : "f"(x));
    return r;
}

__device__ __forceinline__ void mma8(float4& d, uint32_t a0, uint32_t a1,
                                     uint32_t a2, uint32_t a3,
                                     uint32_t b0, uint32_t b1) {
    asm volatile(
        "mma.sync.aligned.m16n8k8.row.col.f32.tf32.tf32.f32 "
        "{%0,%1,%2,%3},{%4,%5,%6,%7},{%8,%9},{%0,%1,%2,%3};"
        : "+f"(d.x), "+f"(d.y), "+f"(d.z), "+f"(d.w)
        : "r"(a0), "r"(a1), "r"(a2), "r"(a3), "r"(b0), "r"(b1));
}
__device__ __forceinline__ void mma16(float4& d, uint32_t a0, uint32_t a1,
                                      uint32_t a2, uint32_t a3,
                                      uint32_t b0, uint32_t b1) {
    asm volatile(
        "mma.sync.aligned.m16n8k16.row.col.f32.f16.f16.f32 "
        "{%0,%1,%2,%3},{%4,%5,%6,%7},{%8,%9},{%0,%1,%2,%3};"
        : "+f"(d.x), "+f"(d.y), "+f"(d.z), "+f"(d.w)
        : "r"(a0), "r"(a1), "r"(a2), "r"(a3), "r"(b0), "r"(b1));
}
__device__ __forceinline__ void ldsm4(uint32_t& r0, uint32_t& r1,
                                      uint32_t& r2, uint32_t& r3, uint32_t a) {
    asm volatile("ldmatrix.sync.aligned.m8n8.x4.shared.b16 {%0,%1,%2,%3}, [%4];"
                 : "=r"(r0), "=r"(r1), "=r"(r2), "=r"(r3) : "r"(a));
}

#define CP_A16(dst_u32, src_ptr) \
    asm volatile("cp.async.ca.shared.global [%0], [%1], 16;" \
                 :: "r"(dst_u32), "l"(src_ptr))
#define CP_COMMIT() asm volatile("cp.async.commit_group;")
#define CP_WAIT0()  asm volatile("cp.async.wait_group 0;" ::: "memory")
#define CP_WAIT1()  asm volatile("cp.async.wait_group 1;" ::: "memory")

// =====================================================================
// Generic conv GEMM (unchanged, proven)
// =====================================================================
template<int KDIM, int OREAL, int EPI, int XSRC, int YDST>
__global__ __launch_bounds__(256)
void k_conv(const float* __restrict__ W, const float* __restrict__ Xp,
            float* __restrict__ Yp,
            const float* __restrict__ e0, const float* __restrict__ e1,
            const float* __restrict__ e2, const float* __restrict__ e3,
            const float* __restrict__ e4) {
    const float* X = (XSRC == 0) ? Xp : (XSRC == 2) ? g_ao : g_fm;
    float* Y = (YDST == 0) ? Yp : (YDST == 1) ? g_h1 : g_fm;

    __shared__ float sw[64 * WT_STR];
    __shared__ float sx[32 * XT_STR];

    int tid = threadIdx.x, wid = tid >> 5, lane = tid & 31;
    int gid = lane >> 2, tig = lane & 3;
    int p0 = blockIdx.x * 128, bo0 = blockIdx.y * 64;
    int mo0 = (wid >> 1) * 16, np0 = (wid & 1) * 64;

    constexpr int NC = KDIM / 32;

    int wrow[2], wcol[2], xrow[4], xcol[4];
#pragma unroll
    for (int q = 0; q < 2; q++) { int f = q * 256 + tid; wrow[q] = f >> 3; wcol[q] = (f & 7) * 4; }
#pragma unroll
    for (int q = 0; q < 4; q++) { int f = q * 256 + tid; xrow[q] = f >> 5; xcol[q] = (f & 31) * 4; }

    float4 rw[2], rx[4];
#pragma unroll
    for (int q = 0; q < 2; q++) {
        if (OREAL % 64 == 0 || bo0 + wrow[q] < OREAL)
            rw[q] = *(const float4*)&W[(bo0 + wrow[q]) * KDIM + wcol[q]];
        else rw[q] = make_float4(0.f, 0.f, 0.f, 0.f);
    }
#pragma unroll
    for (int q = 0; q < 4; q++)
        rx[q] = *(const float4*)&X[xrow[q] * HW + p0 + xcol[q]];

    float4 acc[8];
#pragma unroll
    for (int nt = 0; nt < 8; nt++) acc[nt] = make_float4(0.f, 0.f, 0.f, 0.f);

    const uint32_t* swu = (const uint32_t*)sw;
    const uint32_t* sxu = (const uint32_t*)sx;

    for (int ch = 0; ch < NC; ch++) {
        __syncthreads();
#pragma unroll
        for (int q = 0; q < 2; q++)
            *(float4*)&sw[wrow[q] * WT_STR + wcol[q]] = f2tf4(rw[q]);
#pragma unroll
        for (int q = 0; q < 4; q++)
            *(float4*)&sx[xrow[q] * XT_STR + xcol[q]] = f2tf4(rx[q]);
        __syncthreads();

        if (ch + 1 < NC) {
            int c0 = (ch + 1) * 32;
#pragma unroll
            for (int q = 0; q < 2; q++) {
                if (OREAL % 64 == 0 || bo0 + wrow[q] < OREAL)
                    rw[q] = *(const float4*)&W[(bo0 + wrow[q]) * KDIM + c0 + wcol[q]];
                else rw[q] = make_float4(0.f, 0.f, 0.f, 0.f);
            }
#pragma unroll
            for (int q = 0; q < 4; q++)
                rx[q] = *(const float4*)&X[(c0 + xrow[q]) * HW + p0 + xcol[q]];
        }

#pragma unroll
        for (int kk = 0; kk < 4; kk++) {
            int ca = kk * 8;
            uint32_t a0 = swu[(mo0 + gid) * WT_STR + ca + tig];
            uint32_t a1 = swu[(mo0 + gid + 8) * WT_STR + ca + tig];
            uint32_t a2 = swu[(mo0 + gid) * WT_STR + ca + tig + 4];
            uint32_t a3 = swu[(mo0 + gid + 8) * WT_STR + ca + tig + 4];
#pragma unroll
            for (int nt = 0; nt < 8; nt++) {
                uint32_t b0 = sxu[(ca + tig) * XT_STR + np0 + nt * 8 + gid];
                uint32_t b1 = sxu[(ca + tig + 4) * XT_STR + np0 + nt * 8 + gid];
                mma8(acc[nt], a0, a1, a2, a3, b0, b1);
            }
        }
    }

    int ra = bo0 + mo0 + gid, rb = ra + 8;
    float sca = 0.f, ofa = 0.f, scb = 0.f, ofb = 0.f;
    if (EPI == 0 || EPI == 1) {
        sca = e0[ra] * rsqrtf(e3[ra] + EPS); ofa = e1[ra] - e2[ra] * sca;
        scb = e0[rb] * rsqrtf(e3[rb] + EPS); ofb = e1[rb] - e2[rb] * scb;
    } else {
        sca = 1.f; scb = 1.f;
        ofa = (OREAL % 64 == 0 || ra < OREAL) ? e0[ra] : 0.f;
        ofb = (OREAL % 64 == 0 || rb < OREAL) ? e0[rb] : 0.f;
    }
#pragma unroll
    for (int nt = 0; nt < 8; nt++) {
        int p = p0 + np0 + nt * 8 + 2 * tig;
        float2 va, vb;
        va.x = acc[nt].x * sca + ofa; va.y = acc[nt].y * sca + ofa;
        vb.x = acc[nt].z * scb + ofb; vb.y = acc[nt].w * scb + ofb;
        if (EPI == 1) {
            float2 xa = *(const float2*)&e4[ra * HW + p];
            float2 xb = *(const float2*)&e4[rb * HW + p];
            va.x += xa.x; va.y += xa.y; vb.x += xb.x; vb.y += xb.y;
        }
        if (EPI != 2) {
            va.x = fmaxf(va.x, 0.f); va.y = fmaxf(va.y, 0.f);
            vb.x = fmaxf(vb.x, 0.f); vb.y = fmaxf(vb.y, 0.f);
        }
        if (OREAL % 64 == 0 || ra < OREAL) *(float2*)&Y[ra * HW + p] = va;
        if (OREAL % 64 == 0 || rb < OREAL) *(float2*)&Y[rb * HW + p] = vb;
    }
}

// =====================================================================
// Pack rel_w/rel_h into one fp16 table (288 rows x 128)
// =====================================================================
__global__ void k_relcvt(const float* __restrict__ rel_h,
                         const float* __restrict__ rel_w) {
    int idx = blockIdx.x * 256 + threadIdx.x;
    if (idx >= NREL * DH) return;
    int j = idx >> 7, d = idx & 127;
    float v = 0.f;
    if (j < 191)       v = rel_w[j * DH + d];
    else if (j >= 192 && j < 287) v = rel_h[(j - 192) * DH + d];
    g_relh[idx] = __float2half(v);
}

// =====================================================================
// k_qkv (unchanged from R11)
// =====================================================================
__global__ __launch_bounds__(256)
void k_qkvmma(const float* __restrict__ W) {
    __shared__ float sw[64 * WT_STR];
    __shared__ float sx[32 * XT_STR];

    int tid = threadIdx.x, wid = tid >> 5, lane = tid & 31;
    int gid = lane >> 2, tig = lane & 3;
    int p0 = blockIdx.x * 128, bo0 = blockIdx.y * 64;
    int mp0 = wid * 16;

    int wrow[2], wcol[2], xrow[4], xcol[4];
#pragma unroll
    for (int q = 0; q < 2; q++) { int f = q * 256 + tid; wrow[q] = f >> 3; wcol[q] = (f & 7) * 4; }
#pragma unroll
    for (int q = 0; q < 4; q++) { int f = q * 256 + tid; xrow[q] = f >> 5; xcol[q] = (f & 31) * 4; }

    float4 rw[2], rx[4];
#pragma unroll
    for (int q = 0; q < 2; q++)
        rw[q] = *(const float4*)&W[(bo0 + wrow[q]) * C_ATT + wcol[q]];
#pragma unroll
    for (int q = 0; q < 4; q++)
        rx[q] = *(const float4*)&g_h1[xrow[q] * HW + p0 + xcol[q]];

    float4 acc[8];
#pragma unroll
    for (int nt = 0; nt < 8; nt++) acc[nt] = make_float4(0.f, 0.f, 0.f, 0.f);

    const uint32_t* swu = (const uint32_t*)sw;
    const uint32_t* sxu = (const uint32_t*)sx;

    for (int ch = 0; ch < 2; ch++) {
        __syncthreads();
#pragma unroll
        for (int q = 0; q < 2; q++)
            *(float4*)&sw[wrow[q] * WT_STR + wcol[q]] = f2tf4(rw[q]);
#pragma unroll
        for (int q = 0; q < 4; q++)
            *(float4*)&sx[xrow[q] * XT_STR + xcol[q]] = f2tf4(rx[q]);
        __syncthreads();
        if (ch == 0) {
#pragma unroll
            for (int q = 0; q < 2; q++)
                rw[q] = *(const float4*)&W[(bo0 + wrow[q]) * C_ATT + 32 + wcol[q]];
#pragma unroll
            for (int q = 0; q < 4; q++)
                rx[q] = *(const float4*)&g_h1[(32 + xrow[q]) * HW + p0 + xcol[q]];
        }
#pragma unroll
        for (int kk = 0; kk < 4; kk++) {
            int ca = kk * 8;
            uint32_t a0 = sxu[(ca + tig) * XT_STR + mp0 + gid];
            uint32_t a1 = sxu[(ca + tig) * XT_STR + mp0 + gid + 8];
            uint32_t a2 = sxu[(ca + tig + 4) * XT_STR + mp0 + gid];
            uint32_t a3 = sxu[(ca + tig + 4) * XT_STR + mp0 + gid + 8];
#pragma unroll
            for (int nt = 0; nt < 8; nt++) {
                uint32_t b0 = swu[(nt * 8 + gid) * WT_STR + ca + tig];
                uint32_t b1 = swu[(nt * 8 + gid) * WT_STR + ca + tig + 4];
                mma8(acc[nt], a0, a1, a2, a3, b0, b1);
            }
        }
    }

    int part = bo0 >> 9;
    int head = (bo0 & 511) >> 7;
    int dh0  = bo0 & 127;
    int pa = p0 + mp0 + gid, pb = pa + 8;
#pragma unroll
    for (int nt = 0; nt < 8; nt++) {
        int dh = dh0 + nt * 8 + 2 * tig;
        float ax = acc[nt].x, ay = acc[nt].y, bx = acc[nt].z, by = acc[nt].w;
        if (part == 0) {
            const float sc = 0.08838834764831845f * 1.4426950408889634f;
            ax *= sc; ay *= sc; bx *= sc; by *= sc;
            *(uint32_t*)&g_qh[(head * HW + pa) * DH + dh] = packh2(ax, ay);
            *(uint32_t*)&g_qh[(head * HW + pb) * DH + dh] = packh2(bx, by);
        } else if (part == 1) {
            *(uint32_t*)&g_kh[(head * HW + pa) * DH + dh] = packh2(ax, ay);
            *(uint32_t*)&g_kh[(head * HW + pb) * DH + dh] = packh2(bx, by);
        } else {
            g_vT[(head * DH + dh)     * HW + pa] = __float2half(ax);
            g_vT[(head * DH + dh + 1) * HW + pa] = __float2half(ay);
            g_vT[(head * DH + dh)     * HW + pb] = __float2half(bx);
            g_vT[(head * DH + dh + 1) * HW + pb] = __float2half(by);
        }
    }
}

// =====================================================================
// k_rel (unchanged from R11)
// =====================================================================
__global__ __launch_bounds__(128)
void k_rel() {
    extern __shared__ char smc[];
    __half* qsh = (__half*)smc;
    __half* rsh = (__half*)(smc + 17408);

    int tid = threadIdx.x, wid = tid >> 5, lane = tid & 31;
    int gid = lane >> 2, tig = lane & 3;
    int h = blockIdx.y, r0 = blockIdx.x * 64, c0 = blockIdx.z * 144;
    int wr0 = wid * 16;

    uint32_t q_sm = (uint32_t)__cvta_generic_to_shared(qsh);
    uint32_t r_sm = (uint32_t)__cvta_generic_to_shared(rsh);

    const __half* gq = g_qh + (h * HW + r0) * DH;
    for (int e = tid; e < 64 * 16; e += 128) {
        int r = e >> 4, c = e & 15;
        CP_A16(q_sm + r * 272 + c * 16, gq + r * DH + c * 8);
    }
    const __half* gr = g_relh + c0 * DH;
    for (int e = tid; e < 144 * 16; e += 128) {
        int r = e >> 4, c = e & 15;
        CP_A16(r_sm + r * 272 + c * 16, gr + r * DH + c * 8);
    }
    CP_COMMIT(); CP_WAIT0();
    __syncthreads();

    uint32_t qf[8][4];
    const uint32_t* qw = (const uint32_t*)qsh;
#pragma unroll
    for (int kk = 0; kk < 8; kk++) {
        int cw = kk * 8 + tig;
        qf[kk][0] = qw[(wr0 + gid) * QK_STRW + cw];
        qf[kk][1] = qw[(wr0 + gid + 8) * QK_STRW + cw];
        qf[kk][2] = qw[(wr0 + gid) * QK_STRW + cw + 4];
        qf[kk][3] = qw[(wr0 + gid + 8) * QK_STRW + cw + 4];
    }

    float4 s[18];
#pragma unroll
    for (int nt = 0; nt < 18; nt++) s[nt] = make_float4(0.f, 0.f, 0.f, 0.f);
    const uint32_t* rw = (const uint32_t*)rsh;
#pragma unroll
    for (int kk = 0; kk < 8; kk++) {
        int cw = kk * 8 + tig;
#pragma unroll
        for (int nt = 0; nt < 18; nt++) {
            uint32_t b0 = rw[(nt * 8 + gid) * QK_STRW + cw];
            uint32_t b1 = rw[(nt * 8 + gid) * QK_STRW + cw + 4];
            mma16(s[nt], qf[kk][0], qf[kk][1], qf[kk][2], qf[kk][3], b0, b1);
        }
    }

    int ia = h * HW + r0 + wr0 + gid;
    int ib = ia + 8;
#pragma unroll
    for (int nt = 0; nt < 18; nt++) {
        int j = c0 + nt * 8 + 2 * tig;
        if (j < 192) {
            *(float2*)&g_Rw[ia * 192 + j] = make_float2(s[nt].x, s[nt].y);
            *(float2*)&g_Rw[ib * 192 + j] = make_float2(s[nt].z, s[nt].w);
        } else {
            int j2 = j - 192;
            *(float2*)&g_Rh[ia * 96 + j2] = make_float2(s[nt].x, s[nt].y);
            *(float2*)&g_Rh[ib * 96 + j2] = make_float2(s[nt].z, s[nt].w);
        }
    }
}

// =====================================================================
// Kernel C: flash attention — ldmatrix.x4 b-frag loads (R13).
// =====================================================================
__global__ __launch_bounds__(128, 2)
void k_attn() {
    extern __shared__ char smc[];
    // [0,17408) K buf0 ; [17408,35840) V buf0 ; [35840,54272) V buf1
    // [54272,71680) Q staging == K buf1 ; [71680,96768) Bw ; [96768,109568) Bh
    float* Bw = (float*)(smc + 71680);
    float* Bh = (float*)(smc + 96768);

    uint32_t base = (uint32_t)__cvta_generic_to_shared(smc);
    uint32_t k_sm[2] = { base,         base + 54272 };
    uint32_t v_sm[2] = { base + 17408, base + 35840 };

    int tid  = threadIdx.x;
    int h    = blockIdx.y;
    int r0   = blockIdx.x * TQ;
    int wid  = tid >> 5, lane = tid & 31;
    int gid  = lane >> 2, tig = lane & 3;
    int wr0  = wid * 16;
    int lm   = lane >> 3, lr = lane & 7;           // ldmatrix matrix id / row

    // per-thread intra-group offsets for ldmatrix addressing
    uint32_t koff = (uint32_t)(((lm >> 1) * 8 + lr) * QK_STRB + (lm & 1) * 16);
    uint32_t voff = (uint32_t)(((lm >> 1) * 8 + lr) * VT_STRB + (lm & 1) * 16);
    uint32_t qoff = (uint32_t)(((lm & 1) * 8 + lr + wr0) * QK_STRB + (lm >> 1) * 16);

    const __half* gkh = g_kh + h * HW * DH;
    const __half* gvh = g_vT + h * DH * HW;

    // --- preload Q + tile-0 K/V ---
    {
        const __half* gq = g_qh + (h * HW + r0) * DH;
        uint32_t q_sm = base + 54272;
        for (int e = tid; e < TQ * 16; e += 128) {
            int r = e >> 4, c = e & 15;
            CP_A16(q_sm + r * QK_STRB + c * 16, gq + r * DH + c * 8);
        }
        for (int e = tid; e < TK * 16; e += 128) {
            int r = e >> 4, c = e & 15;
            CP_A16(k_sm[0] + r * QK_STRB + c * 16, gkh + r * DH + c * 8);
        }
        for (int e = tid; e < DH * 8; e += 128) {
            int r = e >> 3, c = e & 7;
            CP_A16(v_sm[0] + r * VT_STRB + c * 16, gvh + r * HW + c * 8);
        }
    }
    CP_COMMIT();

    // --- bias tables: contiguous slice copies from precomputed R ---
    for (int e = tid; e < TQ * WW; e += 128) {
        int r = e / WW, wk = e % WW;
        int i = r0 + r, wq = i % WW;
        Bw[r * BW_STR + wk] = g_Rw[(h * HW + i) * 192 + (WW - 1 - wq) + wk];
    }
    for (int e = tid; e < TQ * HH; e += 128) {
        int r = e / HH, hk = e % HH;
        int i = r0 + r, hq = i / WW;
        Bh[r * BH_STR + hk] = g_Rh[(h * HW + i) * 96 + (HH - 1 - hq) + hk];
    }
    CP_WAIT0();
    __syncthreads();

    // --- Q a-fragments via ldmatrix (a0,a1,a2,a3 = matrices in that order) ---
    uint32_t qf[8][4];
#pragma unroll
    for (int kk = 0; kk < 8; kk++) {
        ldsm4(qf[kk][0], qf[kk][1], qf[kk][2], qf[kk][3],
              base + 54272 + qoff + kk * 32);
    }
    __syncthreads();   // qsh consumed; region is now K buf1

    constexpr int NT = HW / TK;   // 72

    // --- prefetch tile 1 into buf1 ---
    {
        const __half* gk = gkh + TK * DH;
        for (int e = tid; e < TK * 16; e += 128) {
            int r = e >> 4, c = e & 15;
            CP_A16(k_sm[1] + r * QK_STRB + c * 16, gk + r * DH + c * 8);
        }
        const __half* gv = gvh + TK;
        for (int e = tid; e < DH * 8; e += 128) {
            int r = e >> 3, c = e & 7;
            CP_A16(v_sm[1] + r * VT_STRB + c * 16, gv + r * HW + c * 8);
        }
    }
    CP_COMMIT();

    float4 o[16];
#pragma unroll
    for (int nt = 0; nt < 16; nt++) o[nt] = make_float4(0.f, 0.f, 0.f, 0.f);
    float l_a = 0.f, l_b = 0.f;

    int ra = wr0 + gid, rb = ra + 8;

    for (int kt = 0; kt < NT; kt++) {
        int cur = kt & 1;
        if (kt > 0) {
            if (kt + 1 < NT) {
                int nxt = (kt + 1) & 1;
                const __half* gk = gkh + (kt + 1) * TK * DH;
                for (int e = tid; e < TK * 16; e += 128) {
                    int r = e >> 4, c = e & 15;
                    CP_A16(k_sm[nxt] + r * QK_STRB + c * 16, gk + r * DH + c * 8);
                }
                const __half* gv = gvh + (kt + 1) * TK;
                for (int e = tid; e < DH * 8; e += 128) {
                    int r = e >> 3, c = e & 7;
                    CP_A16(v_sm[nxt] + r * VT_STRB + c * 16, gv + r * HW + c * 8);
                }
                CP_COMMIT();
                CP_WAIT1();
            } else {
                CP_WAIT0();
            }
            __syncthreads();
        }

        // --- S = Q @ K^T ; b-frags via ldmatrix.x4 ---
        float4 s[8];
#pragma unroll
        for (int nt = 0; nt < 8; nt++) s[nt] = make_float4(0.f, 0.f, 0.f, 0.f);
        uint32_t kb = k_sm[cur] + koff;
#pragma unroll
        for (int kk = 0; kk < 8; kk++) {
#pragma unroll
            for (int g = 0; g < 4; g++) {
                uint32_t b0, b1, b2, b3;
                ldsm4(b0, b1, b2, b3, kb + g * 16 * QK_STRB + kk * 32);
                mma16(s[2 * g],     qf[kk][0], qf[kk][1], qf[kk][2], qf[kk][3], b0, b1);
                mma16(s[2 * g + 1], qf[kk][0], qf[kk][1], qf[kk][2], qf[kk][3], b2, b3);
            }
        }

        // --- bias add + exp2 (no max subtraction) ---
        int j0 = kt * TK;
        int h0 = j0 / WW, w0 = j0 - WW * h0;
        float bha0 = Bh[ra * BH_STR + h0], bha1 = Bh[ra * BH_STR + h0 + 1];
        float bhb0 = Bh[rb * BH_STR + h0], bhb1 = Bh[rb * BH_STR + h0 + 1];
#pragma unroll
        for (int nt = 0; nt < 8; nt++) {
            int jl = nt * 8 + 2 * tig;
            int w1 = w0 + jl;
            bool wrap = (w1 >= WW);
            int wk0 = wrap ? w1 - WW : w1;
            float bha = wrap ? bha1 : bha0;
            float bhb = wrap ? bhb1 : bhb0;
            float2 ba = *(const float2*)&Bw[ra * BW_STR + wk0];
            float2 bb = *(const float2*)&Bw[rb * BW_STR + wk0];
            s[nt].x = ex2f(s[nt].x + ba.x + bha);
            s[nt].y = ex2f(s[nt].y + ba.y + bha);
            s[nt].z = ex2f(s[nt].z + bb.x + bhb);
            s[nt].w = ex2f(s[nt].w + bb.y + bhb);
            l_a += s[nt].x + s[nt].y;
            l_b += s[nt].z + s[nt].w;
        }

        // --- O += P @ V ; P register-direct, V b-frags via ldmatrix.x4 ---
        uint32_t vb = v_sm[cur] + voff;
#pragma unroll
        for (int kk = 0; kk < 4; kk++) {
            uint32_t a0 = packh2(s[2 * kk].x,     s[2 * kk].y);
            uint32_t a1 = packh2(s[2 * kk].z,     s[2 * kk].w);
            uint32_t a2 = packh2(s[2 * kk + 1].x, s[2 * kk + 1].y);
            uint32_t a3 = packh2(s[2 * kk + 1].z, s[2 * kk + 1].w);
#pragma unroll
            for (int g = 0; g < 8; g++) {
                uint32_t b0, b1, b2, b3;
                ldsm4(b0, b1, b2, b3, vb + g * 16 * VT_STRB + kk * 32);
                mma16(o[2 * g],     a0, a1, a2, a3, b0, b1);
                mma16(o[2 * g + 1], a0, a1, a2, a3, b2, b3);
            }
        }
        __syncthreads();   // buffer `cur` free for prefetch
    }

    // --- epilogue: single l reduction, normalize ---
    l_a += __shfl_xor_sync(0xffffffffu, l_a, 1);
    l_a += __shfl_xor_sync(0xffffffffu, l_a, 2);
    l_b += __shfl_xor_sync(0xffffffffu, l_b, 1);
    l_b += __shfl_xor_sync(0xffffffffu, l_b, 2);
    float inva = 1.f / l_a, invb = 1.f / l_b;
    int ia = r0 + ra, ib = r0 + rb;
#pragma unroll
    for (int nt = 0; nt < 16; nt++) {
        int d = nt * 8 + 2 * tig;
        g_ao[(h * DH + d)     * HW + ia] = o[nt].x * inva;
        g_ao[(h * DH + d + 1) * HW + ia] = o[nt].y * inva;
        g_ao[(h * DH + d)     * HW + ib] = o[nt].z * invb;
        g_ao[(h * DH + d + 1) * HW + ib] = o[nt].w * invb;
    }
}

// ---------------- launch ----------------
extern "C" void kernel_launch(void* const* d_in, const int* in_sizes, int n_in,
                              void* d_out, int out_size) {
    const float* x      = (const float*)d_in[0];
    const float* w_in   = (const float*)d_in[1];
    const float* bn1_g  = (const float*)d_in[2];
    const float* bn1_b  = (const float*)d_in[3];
    const float* bn1_m  = (const float*)d_in[4];
    const float* bn1_v  = (const float*)d_in[5];
    const float* w_qkv  = (const float*)d_in[6];
    const float* rel_h  = (const float*)d_in[7];
    const float* rel_w  = (const float*)d_in[8];
    const float* w_out  = (const float*)d_in[9];
    const float* bn2_g  = (const float*)d_in[10];
    const float* bn2_b  = (const float*)d_in[11];
    const float* bn2_m  = (const float*)d_in[12];
    const float* bn2_v  = (const float*)d_in[13];
    const float* w_head = (const float*)d_in[14];
    const float* b_head = (const float*)d_in[15];
    float* out = (float*)d_out;

    const int ATTN_SMEM = 109568;
    const int REL_SMEM  = 17408 + 144 * 272;   // 56576

    cudaFuncSetAttribute(k_attn, cudaFuncAttributeMaxDynamicSharedMemorySize, ATTN_SMEM);
    cudaFuncSetAttribute(k_rel,  cudaFuncAttributeMaxDynamicSharedMemorySize, REL_SMEM);

    k_relcvt<<<(NREL * DH + 255) / 256, 256>>>(rel_h, rel_w);
    k_conv<256, 64, 0, 0, 1><<<dim3(HW / 128, 1), 256>>>(
        w_in, x, nullptr, bn1_g, bn1_b, bn1_m, bn1_v, nullptr);
    k_qkvmma<<<dim3(HW / 128, (3 * HEADS * DH) / 64), 256>>>(w_qkv);
    k_rel<<<dim3(HW / 64, HEADS, 2), 128, REL_SMEM>>>();
    k_attn<<<dim3(HW / TQ, HEADS), 128, ATTN_SMEM>>>();
    k_conv<512, 256, 1, 2, 3><<<dim3(HW / 128, C_MID / 64), 256>>>(
        w_out, nullptr, nullptr, bn2_g, bn2_b, bn2_m, bn2_v, x);
    k_conv<256, 19, 2, 3, 0><<<dim3(HW / 128, 1), 256>>>(
        w_head, nullptr, out, b_head, nullptr, nullptr, nullptr, nullptr);
}